// round 14
// baseline (speedup 1.0000x reference)
#include <cuda_runtime.h>
#include <cuda_fp16.h>
#include <cstdint>
#include <math.h>

// ============================================================================
// FiLMLSTMCell: B=16384, D_IN=512, H=512
// R13 kernels verbatim, overlapped via graph-capturable stream fork/join:
// GEMM sliced into 8 x 128-CTA slices on the capture stream; each slice's
// tail (2048 rows) runs on a second stream gated by an event. Tail CTAs
// co-reside with GEMM CTAs (regs/smem verified) -> tail hides under GEMM.
// ============================================================================
#define BROWS 16384
#define KDIM  1024
#define NDIM  2048
#define HDIM  512

#define NSLICES 8
#define MB_PER_SLICE 16          // 16 m-blocks * 128 rows = 2048 rows/slice

__device__ __half g_Ah [(size_t)BROWS * KDIM];  // 32 MB fp16 cat(x,h)
__device__ __half g_WTh[(size_t)NDIM * KDIM];   //  4 MB fp16 W^T [N,K]
__device__ __half g_Zh [(size_t)BROWS * NDIM];  // 64 MB fp16 z

__device__ __forceinline__ void mma_f16(float* c,
                                        uint32_t a0, uint32_t a1, uint32_t a2, uint32_t a3,
                                        uint32_t b0, uint32_t b1) {
    asm volatile(
        "mma.sync.aligned.m16n8k16.row.col.f32.f16.f16.f32 "
        "{%0,%1,%2,%3}, {%4,%5,%6,%7}, {%8,%9}, {%0,%1,%2,%3};"
        : "+f"(c[0]), "+f"(c[1]), "+f"(c[2]), "+f"(c[3])
        : "r"(a0), "r"(a1), "r"(a2), "r"(a3), "r"(b0), "r"(b1));
}

__device__ __forceinline__ void ldsm_x4(uint32_t& r0, uint32_t& r1,
                                        uint32_t& r2, uint32_t& r3, uint32_t addr) {
    asm volatile("ldmatrix.sync.aligned.m8n8.x4.shared.b16 {%0,%1,%2,%3}, [%4];"
                 : "=r"(r0), "=r"(r1), "=r"(r2), "=r"(r3) : "r"(addr));
}

__device__ __forceinline__ float sigm(float x) {
    float e, r;
    asm("ex2.approx.f32 %0, %1;" : "=f"(e) : "f"(-1.4426950408889634f * x));
    asm("rcp.approx.f32 %0, %1;" : "=f"(r) : "f"(1.0f + e));
    return r;
}
__device__ __forceinline__ float tanh_a(float x) {
    float r;
    asm("tanh.approx.f32 %0, %1;" : "=f"(r) : "f"(x));
    return r;
}

// ============================================================================
// GEMM (R13 verbatim, + m-block offset): CTA 128x256, BKH=128, 2-stage.
// Swizzle word (row,kp): row*64 + (kp ^ (4*(row&7))).
// ============================================================================
#define BM 128
#define BN 256
#define BKH 128
#define NCHUNK (KDIM / BKH)       // 8
#define STAGES 2

#define A_WORDS (BM * BKH / 2)                 // 8192
#define B_WORDS (BN * BKH / 2)                 // 16384
#define B_BASE  (STAGES * A_WORDS)             // 16384
#define BIAS_BASE (B_BASE + STAGES * B_WORDS)  // 49152
#define GEMM_SMEM ((BIAS_BASE + BN) * 4)       // 197632 B

__device__ __forceinline__ void load_chunk(uint32_t aBase, uint32_t bBase,
                                           const __half* __restrict__ Asrc,
                                           const __half* __restrict__ Bsrc,
                                           int tid) {
    #pragma unroll
    for (int rep = 0; rep < 8; rep++) {
        int idx = rep * 256 + tid;
        int row = idx >> 4, q = idx & 15;
        uint32_t off = (uint32_t)(row * 256 + 16 * (q ^ (row & 7)));
        asm volatile("cp.async.cg.shared.global [%0], [%1], 16;"
                     :: "r"(aBase + off), "l"(Asrc + (size_t)row * KDIM + q * 8));
    }
    #pragma unroll
    for (int rep = 0; rep < 16; rep++) {
        int idx = rep * 256 + tid;
        int row = idx >> 4, q = idx & 15;
        uint32_t off = (uint32_t)(row * 256 + 16 * (q ^ (row & 7)));
        asm volatile("cp.async.cg.shared.global [%0], [%1], 16;"
                     :: "r"(bBase + off), "l"(Bsrc + (size_t)row * KDIM + q * 8));
    }
    asm volatile("cp.async.commit_group;" ::: "memory");
}

__global__ void __launch_bounds__(256, 1)
gemm_mma_kernel(const float* __restrict__ bias, int mb_base) {
    extern __shared__ float sm[];
    float* sBias = sm + BIAS_BASE;

    const int tid = threadIdx.x, wid = tid >> 5, lane = tid & 31;
    const int g = lane >> 2, l4 = lane & 3;
    const int m0 = (blockIdx.y + mb_base) * BM;
    const int n0 = blockIdx.x * BN;
    const int wm = wid & 1, wn = wid >> 1;

    uint32_t sb;
    asm("{ .reg .u64 t; cvta.to.shared.u64 t, %1; cvt.u32.u64 %0, t; }"
        : "=r"(sb) : "l"(sm));

    for (int i = tid; i < BN; i += 256) sBias[i] = bias[n0 + i];

    const int t8 = lane >> 3, rr = lane & 7;
    const int swz = 4 * rr;
    const int rowA = wm * 64 + (t8 & 1) * 8 + rr;
    const int kselA = (t8 >> 1) * 4;
    const int rowB = wn * 64 + (t8 >> 1) * 8 + rr;
    const int kselB = (t8 & 1) * 4;

    float acc[4][8][4];
    #pragma unroll
    for (int a = 0; a < 4; a++)
        #pragma unroll
        for (int b = 0; b < 8; b++)
            #pragma unroll
            for (int d = 0; d < 4; d++) acc[a][b][d] = 0.0f;

    const __half* Ag = g_Ah  + (size_t)m0 * KDIM;
    const __half* Bg = g_WTh + (size_t)n0 * KDIM;

    load_chunk(sb, sb + B_BASE * 4, Ag, Bg, tid);

    for (int kc = 0; kc < NCHUNK; kc++) {
        const int s = kc & 1;
        asm volatile("cp.async.wait_group 0;" ::: "memory");
        __syncthreads();

        if (kc + 1 < NCHUNK) {
            const int sl = (kc + 1) & 1;
            load_chunk(sb + sl * A_WORDS * 4, sb + (B_BASE + sl * B_WORDS) * 4,
                       Ag + (kc + 1) * BKH, Bg + (kc + 1) * BKH, tid);
        }

        const uint32_t aSm = sb + (uint32_t)s * A_WORDS * 4;
        const uint32_t bSm = sb + (uint32_t)(B_BASE + s * B_WORDS) * 4;

        #pragma unroll
        for (int ks = 0; ks < 8; ks++) {
            const int kwA = (ks * 8 + kselA) ^ swz;
            const int kwB = (ks * 8 + kselB) ^ swz;
            uint32_t afr[4][4];
            #pragma unroll
            for (int ms = 0; ms < 4; ms++)
                ldsm_x4(afr[ms][0], afr[ms][1], afr[ms][2], afr[ms][3],
                        aSm + 4u * ((rowA + ms * 16) * 64 + kwA));
            uint32_t bfr[8][2];
            #pragma unroll
            for (int ns2 = 0; ns2 < 4; ns2++)
                ldsm_x4(bfr[2 * ns2][0], bfr[2 * ns2][1],
                        bfr[2 * ns2 + 1][0], bfr[2 * ns2 + 1][1],
                        bSm + 4u * ((rowB + ns2 * 16) * 64 + kwB));
            #pragma unroll
            for (int ms = 0; ms < 4; ms++)
                #pragma unroll
                for (int ns = 0; ns < 8; ns++)
                    mma_f16(acc[ms][ns], afr[ms][0], afr[ms][1], afr[ms][2], afr[ms][3],
                            bfr[ns][0], bfr[ns][1]);
        }
    }

    #pragma unroll
    for (int ms = 0; ms < 4; ms++) {
        const int row = m0 + wm * 64 + ms * 16 + g;
        #pragma unroll
        for (int ns = 0; ns < 8; ns++) {
            const int colL = wn * 64 + ns * 8 + 2 * l4;
            const float b0 = sBias[colL], b1 = sBias[colL + 1];
            __half2 v0 = __floats2half2_rn(acc[ms][ns][0] + b0, acc[ms][ns][1] + b1);
            __half2 v1 = __floats2half2_rn(acc[ms][ns][2] + b0, acc[ms][ns][3] + b1);
            *(__half2*)(g_Zh + (size_t)row       * NDIM + n0 + colL) = v0;
            *(__half2*)(g_Zh + (size_t)(row + 8) * NDIM + n0 + colL) = v1;
        }
    }
}

// ============================================================================
// Prep (merged, R13 verbatim)
// ============================================================================
__global__ void __launch_bounds__(256) prep_kernel(const float* __restrict__ x,
                                                   const float* __restrict__ h,
                                                   const float* __restrict__ W) {
    if (blockIdx.x >= 4096) {
        __shared__ float tile[32][33];
        const int wt = blockIdx.x - 4096;
        const int n0 = (wt & 63) * 32, k0 = (wt >> 6) * 32;
        const int tx = threadIdx.x & 31, ty = threadIdx.x >> 5;
        #pragma unroll
        for (int j = 0; j < 32; j += 8)
            tile[ty + j][tx] = W[(size_t)(k0 + ty + j) * NDIM + n0 + tx];
        __syncthreads();
        #pragma unroll
        for (int j = 0; j < 32; j += 8)
            g_WTh[(size_t)(n0 + ty + j) * KDIM + k0 + tx] =
                __float2half_rn(tile[tx][ty + j]);
        return;
    }
    const int base = (blockIdx.x * 256 + threadIdx.x) * 4;
    #pragma unroll
    for (int it = 0; it < 4; it++) {
        const int i = base + it;
        const int m = i >> 8, t = i & 255;
        float4 v;
        if (t < 128) v = ((const float4*)(x + (size_t)m * 512))[t];
        else         v = ((const float4*)(h + (size_t)m * 512))[t - 128];
        __half2 lo = __floats2half2_rn(v.x, v.y);
        __half2 hi = __floats2half2_rn(v.z, v.w);
        uint2 pk = make_uint2(*(uint32_t*)&lo, *(uint32_t*)&hi);
        ((uint2*)(g_Ah + (size_t)m * KDIM))[t] = pk;
    }
}

// ============================================================================
// Fused tail (R13 verbatim, + row offset)
// ============================================================================
__global__ void __launch_bounds__(256) fused_tail_kernel(
    const float* __restrict__ c, const float* __restrict__ u,
    const float* __restrict__ gamma, const float* __restrict__ beta,
    float* __restrict__ outH, float* __restrict__ outC, int row_base) {
    __shared__ float s_z[2048];
    __shared__ float s_sum[8], s_sq[8], s_sum2[8], s_sq2[8];

    const int row = blockIdx.x + row_base;
    const int t = threadIdx.x, w = t >> 5, lane = t & 31;

    const uint4* zr = (const uint4*)(g_Zh + (size_t)row * 2048);
    const float4* ua = (const float4*)(u + (size_t)row * 4096);
    const float4* ub = (const float4*)(u + (size_t)row * 4096 + 2048);

    uint4 zp = zr[t];
    float2 zf[4];
    zf[0] = __half22float2(*(__half2*)&zp.x);
    zf[1] = __half22float2(*(__half2*)&zp.y);
    zf[2] = __half22float2(*(__half2*)&zp.z);
    zf[3] = __half22float2(*(__half2*)&zp.w);

    float sum = 0.0f, sq = 0.0f;
    #pragma unroll
    for (int q = 0; q < 4; q++) {
        sum += zf[q].x + zf[q].y;
        sq  += zf[q].x * zf[q].x + zf[q].y * zf[q].y;
    }
    #pragma unroll
    for (int o = 16; o; o >>= 1) {
        sum += __shfl_xor_sync(0xFFFFFFFFu, sum, o);
        sq  += __shfl_xor_sync(0xFFFFFFFFu, sq, o);
    }
    if (lane == 0) { s_sum[w] = sum; s_sq[w] = sq; }
    __syncthreads();
    const int grp = t >> 6;
    const float mean = (s_sum[2 * grp] + s_sum[2 * grp + 1]) * (1.0f / 512.0f);
    const float var  = (s_sq[2 * grp] + s_sq[2 * grp + 1]) * (1.0f / 512.0f) - mean * mean;
    const float inv  = rsqrtf(var + 1e-5f);

    float4 a0 = ua[2 * t], a1 = ua[2 * t + 1];
    float4 b0 = ub[2 * t], b1 = ub[2 * t + 1];
    float4 o0, o1;
    o0.x = (zf[0].x - mean) * inv * (1.0f + a0.x) + b0.x;
    o0.y = (zf[0].y - mean) * inv * (1.0f + a0.y) + b0.y;
    o0.z = (zf[1].x - mean) * inv * (1.0f + a0.z) + b0.z;
    o0.w = (zf[1].y - mean) * inv * (1.0f + a0.w) + b0.w;
    o1.x = (zf[2].x - mean) * inv * (1.0f + a1.x) + b1.x;
    o1.y = (zf[2].y - mean) * inv * (1.0f + a1.y) + b1.y;
    o1.z = (zf[3].x - mean) * inv * (1.0f + a1.z) + b1.z;
    o1.w = (zf[3].y - mean) * inv * (1.0f + a1.w) + b1.w;
    ((float4*)s_z)[2 * t] = o0;
    ((float4*)s_z)[2 * t + 1] = o1;
    __syncthreads();

    const int j = 2 * t;
    float2 iz = *(const float2*)&s_z[j];
    float2 fz = *(const float2*)&s_z[512 + j];
    float2 gz = *(const float2*)&s_z[1536 + j];
    float2 cv = *(const float2*)(c + (size_t)row * 512 + j);
    float cn0 = sigm(fz.x) * cv.x + sigm(iz.x) * tanh_a(gz.x);
    float cn1 = sigm(fz.y) * cv.y + sigm(iz.y) * tanh_a(gz.y);
    *(float2*)(outC + (size_t)row * 512 + j) = make_float2(cn0, cn1);

    float sum2 = cn0 + cn1, sq2 = cn0 * cn0 + cn1 * cn1;
    #pragma unroll
    for (int o = 16; o; o >>= 1) {
        sum2 += __shfl_xor_sync(0xFFFFFFFFu, sum2, o);
        sq2  += __shfl_xor_sync(0xFFFFFFFFu, sq2, o);
    }
    if (lane == 0) { s_sum2[w] = sum2; s_sq2[w] = sq2; }
    __syncthreads();

    float ts = 0.0f, tq = 0.0f;
    #pragma unroll
    for (int k = 0; k < 8; k++) { ts += s_sum2[k]; tq += s_sq2[k]; }
    const float m2 = ts * (1.0f / 512.0f);
    const float v2 = tq * (1.0f / 512.0f) - m2 * m2;
    const float inv2 = rsqrtf(v2 + 1e-5f);
    float2 gm = *(const float2*)(gamma + j);
    float2 bt = *(const float2*)(beta + j);
    float cnn0 = (cn0 - m2) * inv2 * gm.x + bt.x;
    float cnn1 = (cn1 - m2) * inv2 * gm.y + bt.y;
    float2 oz = *(const float2*)&s_z[1024 + j];
    float h0 = sigm(oz.x) * tanh_a(cnn0);
    float h1 = sigm(oz.y) * tanh_a(cnn1);
    *(float2*)(outH + (size_t)row * 512 + j) = make_float2(h0, h1);
}

// ============================================================================
// Stream/event resources — created at static init (before the harness's
// memory baseline; nothing allocated inside kernel_launch).
// ============================================================================
static cudaStream_t g_s2 = nullptr;
static cudaEvent_t  g_evG[NSLICES];
static cudaEvent_t  g_evJoin = nullptr;
static struct StreamInit {
    StreamInit() {
        cudaStreamCreateWithFlags(&g_s2, cudaStreamNonBlocking);
        for (int i = 0; i < NSLICES; i++)
            cudaEventCreateWithFlags(&g_evG[i], cudaEventDisableTiming);
        cudaEventCreateWithFlags(&g_evJoin, cudaEventDisableTiming);
    }
} g_streamInit;

// ============================================================================
// kernel_launch: prep -> 8x { gemm slice ; event ; tail slice on s2 } -> join
// ============================================================================
extern "C" void kernel_launch(void* const* d_in, const int* in_sizes, int n_in,
                              void* d_out, int out_size) {
    const float* x     = (const float*)d_in[0];
    const float* h     = (const float*)d_in[1];
    const float* c     = (const float*)d_in[2];
    const float* u     = (const float*)d_in[3];
    const float* W     = (const float*)d_in[4];
    const float* blin  = (const float*)d_in[5];
    const float* gamma = (const float*)d_in[6];
    const float* beta  = (const float*)d_in[7];
    float* outH = (float*)d_out;
    float* outC = (float*)d_out + (size_t)BROWS * HDIM;

    cudaFuncSetAttribute(gemm_mma_kernel,
                         cudaFuncAttributeMaxDynamicSharedMemorySize, GEMM_SMEM);

    prep_kernel<<<4096 + 2048, 256>>>(x, h, W);

    for (int i = 0; i < NSLICES; i++) {
        gemm_mma_kernel<<<dim3(NDIM / BN, MB_PER_SLICE), 256, GEMM_SMEM>>>(
            blin, i * MB_PER_SLICE);
        cudaEventRecord(g_evG[i], 0);
        cudaStreamWaitEvent(g_s2, g_evG[i], 0);
        fused_tail_kernel<<<BROWS / NSLICES, 256, 0, g_s2>>>(
            c, u, gamma, beta, outH, outC, i * (BROWS / NSLICES));
    }
    cudaEventRecord(g_evJoin, g_s2);
    cudaStreamWaitEvent(0, g_evJoin, 0);
}

// round 15
// speedup vs baseline: 1.1289x; 1.1289x over previous
#include <cuda_runtime.h>
#include <cuda_fp16.h>
#include <cstdint>
#include <math.h>

// ============================================================================
// FiLMLSTMCell: B=16384, D_IN=512, H=512
// R14 ncu showed tensor=50.1% @ occ 12.1% (2 warps/SMSP): the fp16 mma.sync
// GEMM was ISSUE-bound, not tensor-rt-bound. This round: 512 threads/CTA
// (16 warps, 4Mx4N, warp tile 32x64) -> 4 warps/SMSP to fill the bubbles.
// Same CTA tile 128x256, same smem/pipeline. Prep+tail = R13 verbatim.
// ============================================================================
#define BROWS 16384
#define KDIM  1024
#define NDIM  2048
#define HDIM  512

__device__ __half g_Ah [(size_t)BROWS * KDIM];  // 32 MB fp16 cat(x,h)
__device__ __half g_WTh[(size_t)NDIM * KDIM];   //  4 MB fp16 W^T [N,K]
__device__ __half g_Zh [(size_t)BROWS * NDIM];  // 64 MB fp16 z

__device__ __forceinline__ void mma_f16(float* c,
                                        uint32_t a0, uint32_t a1, uint32_t a2, uint32_t a3,
                                        uint32_t b0, uint32_t b1) {
    asm volatile(
        "mma.sync.aligned.m16n8k16.row.col.f32.f16.f16.f32 "
        "{%0,%1,%2,%3}, {%4,%5,%6,%7}, {%8,%9}, {%0,%1,%2,%3};"
        : "+f"(c[0]), "+f"(c[1]), "+f"(c[2]), "+f"(c[3])
        : "r"(a0), "r"(a1), "r"(a2), "r"(a3), "r"(b0), "r"(b1));
}

__device__ __forceinline__ void ldsm_x4(uint32_t& r0, uint32_t& r1,
                                        uint32_t& r2, uint32_t& r3, uint32_t addr) {
    asm volatile("ldmatrix.sync.aligned.m8n8.x4.shared.b16 {%0,%1,%2,%3}, [%4];"
                 : "=r"(r0), "=r"(r1), "=r"(r2), "=r"(r3) : "r"(addr));
}

__device__ __forceinline__ float sigm(float x) {
    float e, r;
    asm("ex2.approx.f32 %0, %1;" : "=f"(e) : "f"(-1.4426950408889634f * x));
    asm("rcp.approx.f32 %0, %1;" : "=f"(r) : "f"(1.0f + e));
    return r;
}
__device__ __forceinline__ float tanh_a(float x) {
    float r;
    asm("tanh.approx.f32 %0, %1;" : "=f"(r) : "f"(x));
    return r;
}

// ============================================================================
// GEMM: CTA 128(M) x 256(N), BKH=128 (256B rows), 512 threads (16 warps,
// 4Mx4N, warp tile 32x64), 2-stage cp.async, 8 chunks.
// Swizzle word (row,kp): row*64 + (kp ^ (4*(row&7))) -> conflict-free LDSM.
// ============================================================================
#define BM 128
#define BN 256
#define BKH 128
#define NCHUNK (KDIM / BKH)       // 8
#define STAGES 2

#define A_WORDS (BM * BKH / 2)                 // 8192 words (32KB)
#define B_WORDS (BN * BKH / 2)                 // 16384 (64KB)
#define B_BASE  (STAGES * A_WORDS)             // 16384
#define BIAS_BASE (B_BASE + STAGES * B_WORDS)  // 49152
#define GEMM_SMEM ((BIAS_BASE + BN) * 4)       // 197632 B

__device__ __forceinline__ void load_chunk(uint32_t aBase, uint32_t bBase,
                                           const __half* __restrict__ Asrc,
                                           const __half* __restrict__ Bsrc,
                                           int tid) {
    #pragma unroll
    for (int rep = 0; rep < 4; rep++) {     // A: 128 rows x 16 16B-chunks
        int idx = rep * 512 + tid;
        int row = idx >> 4, q = idx & 15;
        uint32_t off = (uint32_t)(row * 256 + 16 * (q ^ (row & 7)));
        asm volatile("cp.async.cg.shared.global [%0], [%1], 16;"
                     :: "r"(aBase + off), "l"(Asrc + (size_t)row * KDIM + q * 8));
    }
    #pragma unroll
    for (int rep = 0; rep < 8; rep++) {     // B: 256 rows x 16
        int idx = rep * 512 + tid;
        int row = idx >> 4, q = idx & 15;
        uint32_t off = (uint32_t)(row * 256 + 16 * (q ^ (row & 7)));
        asm volatile("cp.async.cg.shared.global [%0], [%1], 16;"
                     :: "r"(bBase + off), "l"(Bsrc + (size_t)row * KDIM + q * 8));
    }
    asm volatile("cp.async.commit_group;" ::: "memory");
}

__global__ void __launch_bounds__(512, 1)
gemm_mma_kernel(const float* __restrict__ bias) {
    extern __shared__ float sm[];
    float* sBias = sm + BIAS_BASE;

    const int tid = threadIdx.x, wid = tid >> 5, lane = tid & 31;
    const int g = lane >> 2, l4 = lane & 3;
    const int m0 = blockIdx.y * BM;
    const int n0 = blockIdx.x * BN;
    const int wm = wid & 3, wn = wid >> 2;   // 4M x 4N warps, tile 32x64

    uint32_t sb;
    asm("{ .reg .u64 t; cvta.to.shared.u64 t, %1; cvt.u32.u64 %0, t; }"
        : "=r"(sb) : "l"(sm));

    for (int i = tid; i < BN; i += 512) sBias[i] = bias[n0 + i];

    const int t8 = lane >> 3, rr = lane & 7;
    const int swz = 4 * rr;
    const int rowA = wm * 32 + (t8 & 1) * 8 + rr;    // + ms*16, ms in {0,1}
    const int kselA = (t8 >> 1) * 4;
    const int rowB = wn * 64 + (t8 >> 1) * 8 + rr;   // + ns2*16
    const int kselB = (t8 & 1) * 4;

    float acc[2][8][4];
    #pragma unroll
    for (int a = 0; a < 2; a++)
        #pragma unroll
        for (int b = 0; b < 8; b++)
            #pragma unroll
            for (int d = 0; d < 4; d++) acc[a][b][d] = 0.0f;

    const __half* Ag = g_Ah  + (size_t)m0 * KDIM;
    const __half* Bg = g_WTh + (size_t)n0 * KDIM;

    load_chunk(sb, sb + B_BASE * 4, Ag, Bg, tid);

    for (int kc = 0; kc < NCHUNK; kc++) {
        const int s = kc & 1;
        asm volatile("cp.async.wait_group 0;" ::: "memory");
        __syncthreads();

        if (kc + 1 < NCHUNK) {
            const int sl = (kc + 1) & 1;
            load_chunk(sb + sl * A_WORDS * 4, sb + (B_BASE + sl * B_WORDS) * 4,
                       Ag + (kc + 1) * BKH, Bg + (kc + 1) * BKH, tid);
        }

        const uint32_t aSm = sb + (uint32_t)s * A_WORDS * 4;
        const uint32_t bSm = sb + (uint32_t)(B_BASE + s * B_WORDS) * 4;

        #pragma unroll
        for (int ks = 0; ks < 8; ks++) {
            const int kwA = (ks * 8 + kselA) ^ swz;
            const int kwB = (ks * 8 + kselB) ^ swz;
            uint32_t afr[2][4];
            #pragma unroll
            for (int ms = 0; ms < 2; ms++)
                ldsm_x4(afr[ms][0], afr[ms][1], afr[ms][2], afr[ms][3],
                        aSm + 4u * ((rowA + ms * 16) * 64 + kwA));
            uint32_t bfr[8][2];
            #pragma unroll
            for (int ns2 = 0; ns2 < 4; ns2++)
                ldsm_x4(bfr[2 * ns2][0], bfr[2 * ns2][1],
                        bfr[2 * ns2 + 1][0], bfr[2 * ns2 + 1][1],
                        bSm + 4u * ((rowB + ns2 * 16) * 64 + kwB));
            #pragma unroll
            for (int ms = 0; ms < 2; ms++)
                #pragma unroll
                for (int ns = 0; ns < 8; ns++)
                    mma_f16(acc[ms][ns], afr[ms][0], afr[ms][1], afr[ms][2], afr[ms][3],
                            bfr[ns][0], bfr[ns][1]);
        }
    }

    // Epilogue: + bias, fp16 z store
    #pragma unroll
    for (int ms = 0; ms < 2; ms++) {
        const int row = m0 + wm * 32 + ms * 16 + g;
        #pragma unroll
        for (int ns = 0; ns < 8; ns++) {
            const int colL = wn * 64 + ns * 8 + 2 * l4;
            const float b0 = sBias[colL], b1 = sBias[colL + 1];
            __half2 v0 = __floats2half2_rn(acc[ms][ns][0] + b0, acc[ms][ns][1] + b1);
            __half2 v1 = __floats2half2_rn(acc[ms][ns][2] + b0, acc[ms][ns][3] + b1);
            *(__half2*)(g_Zh + (size_t)row       * NDIM + n0 + colL) = v0;
            *(__half2*)(g_Zh + (size_t)(row + 8) * NDIM + n0 + colL) = v1;
        }
    }
}

// ============================================================================
// Prep (merged, R13 verbatim)
// ============================================================================
__global__ void __launch_bounds__(256) prep_kernel(const float* __restrict__ x,
                                                   const float* __restrict__ h,
                                                   const float* __restrict__ W) {
    if (blockIdx.x >= 4096) {
        __shared__ float tile[32][33];
        const int wt = blockIdx.x - 4096;
        const int n0 = (wt & 63) * 32, k0 = (wt >> 6) * 32;
        const int tx = threadIdx.x & 31, ty = threadIdx.x >> 5;
        #pragma unroll
        for (int j = 0; j < 32; j += 8)
            tile[ty + j][tx] = W[(size_t)(k0 + ty + j) * NDIM + n0 + tx];
        __syncthreads();
        #pragma unroll
        for (int j = 0; j < 32; j += 8)
            g_WTh[(size_t)(n0 + ty + j) * KDIM + k0 + tx] =
                __float2half_rn(tile[tx][ty + j]);
        return;
    }
    const int base = (blockIdx.x * 256 + threadIdx.x) * 4;
    #pragma unroll
    for (int it = 0; it < 4; it++) {
        const int i = base + it;
        const int m = i >> 8, t = i & 255;
        float4 v;
        if (t < 128) v = ((const float4*)(x + (size_t)m * 512))[t];
        else         v = ((const float4*)(h + (size_t)m * 512))[t - 128];
        __half2 lo = __floats2half2_rn(v.x, v.y);
        __half2 hi = __floats2half2_rn(v.z, v.w);
        uint2 pk = make_uint2(*(uint32_t*)&lo, *(uint32_t*)&hi);
        ((uint2*)(g_Ah + (size_t)m * KDIM))[t] = pk;
    }
}

// ============================================================================
// Fused tail (R13 verbatim)
// ============================================================================
__global__ void __launch_bounds__(256) fused_tail_kernel(
    const float* __restrict__ c, const float* __restrict__ u,
    const float* __restrict__ gamma, const float* __restrict__ beta,
    float* __restrict__ outH, float* __restrict__ outC) {
    __shared__ float s_z[2048];
    __shared__ float s_sum[8], s_sq[8], s_sum2[8], s_sq2[8];

    const int row = blockIdx.x;
    const int t = threadIdx.x, w = t >> 5, lane = t & 31;

    const uint4* zr = (const uint4*)(g_Zh + (size_t)row * 2048);
    const float4* ua = (const float4*)(u + (size_t)row * 4096);
    const float4* ub = (const float4*)(u + (size_t)row * 4096 + 2048);

    uint4 zp = zr[t];
    float2 zf[4];
    zf[0] = __half22float2(*(__half2*)&zp.x);
    zf[1] = __half22float2(*(__half2*)&zp.y);
    zf[2] = __half22float2(*(__half2*)&zp.z);
    zf[3] = __half22float2(*(__half2*)&zp.w);

    float sum = 0.0f, sq = 0.0f;
    #pragma unroll
    for (int q = 0; q < 4; q++) {
        sum += zf[q].x + zf[q].y;
        sq  += zf[q].x * zf[q].x + zf[q].y * zf[q].y;
    }
    #pragma unroll
    for (int o = 16; o; o >>= 1) {
        sum += __shfl_xor_sync(0xFFFFFFFFu, sum, o);
        sq  += __shfl_xor_sync(0xFFFFFFFFu, sq, o);
    }
    if (lane == 0) { s_sum[w] = sum; s_sq[w] = sq; }
    __syncthreads();
    const int grp = t >> 6;
    const float mean = (s_sum[2 * grp] + s_sum[2 * grp + 1]) * (1.0f / 512.0f);
    const float var  = (s_sq[2 * grp] + s_sq[2 * grp + 1]) * (1.0f / 512.0f) - mean * mean;
    const float inv  = rsqrtf(var + 1e-5f);

    float4 a0 = ua[2 * t], a1 = ua[2 * t + 1];
    float4 b0 = ub[2 * t], b1 = ub[2 * t + 1];
    float4 o0, o1;
    o0.x = (zf[0].x - mean) * inv * (1.0f + a0.x) + b0.x;
    o0.y = (zf[0].y - mean) * inv * (1.0f + a0.y) + b0.y;
    o0.z = (zf[1].x - mean) * inv * (1.0f + a0.z) + b0.z;
    o0.w = (zf[1].y - mean) * inv * (1.0f + a0.w) + b0.w;
    o1.x = (zf[2].x - mean) * inv * (1.0f + a1.x) + b1.x;
    o1.y = (zf[2].y - mean) * inv * (1.0f + a1.y) + b1.y;
    o1.z = (zf[3].x - mean) * inv * (1.0f + a1.z) + b1.z;
    o1.w = (zf[3].y - mean) * inv * (1.0f + a1.w) + b1.w;
    ((float4*)s_z)[2 * t] = o0;
    ((float4*)s_z)[2 * t + 1] = o1;
    __syncthreads();

    const int j = 2 * t;
    float2 iz = *(const float2*)&s_z[j];
    float2 fz = *(const float2*)&s_z[512 + j];
    float2 gz = *(const float2*)&s_z[1536 + j];
    float2 cv = *(const float2*)(c + (size_t)row * 512 + j);
    float cn0 = sigm(fz.x) * cv.x + sigm(iz.x) * tanh_a(gz.x);
    float cn1 = sigm(fz.y) * cv.y + sigm(iz.y) * tanh_a(gz.y);
    *(float2*)(outC + (size_t)row * 512 + j) = make_float2(cn0, cn1);

    float sum2 = cn0 + cn1, sq2 = cn0 * cn0 + cn1 * cn1;
    #pragma unroll
    for (int o = 16; o; o >>= 1) {
        sum2 += __shfl_xor_sync(0xFFFFFFFFu, sum2, o);
        sq2  += __shfl_xor_sync(0xFFFFFFFFu, sq2, o);
    }
    if (lane == 0) { s_sum2[w] = sum2; s_sq2[w] = sq2; }
    __syncthreads();

    float ts = 0.0f, tq = 0.0f;
    #pragma unroll
    for (int k = 0; k < 8; k++) { ts += s_sum2[k]; tq += s_sq2[k]; }
    const float m2 = ts * (1.0f / 512.0f);
    const float v2 = tq * (1.0f / 512.0f) - m2 * m2;
    const float inv2 = rsqrtf(v2 + 1e-5f);
    float2 gm = *(const float2*)(gamma + j);
    float2 bt = *(const float2*)(beta + j);
    float cnn0 = (cn0 - m2) * inv2 * gm.x + bt.x;
    float cnn1 = (cn1 - m2) * inv2 * gm.y + bt.y;
    float2 oz = *(const float2*)&s_z[1024 + j];
    float h0 = sigm(oz.x) * tanh_a(cnn0);
    float h1 = sigm(oz.y) * tanh_a(cnn1);
    *(float2*)(outH + (size_t)row * 512 + j) = make_float2(h0, h1);
}

// ============================================================================
// kernel_launch (R13 structure: 3 launches, single stream)
// ============================================================================
extern "C" void kernel_launch(void* const* d_in, const int* in_sizes, int n_in,
                              void* d_out, int out_size) {
    const float* x     = (const float*)d_in[0];
    const float* h     = (const float*)d_in[1];
    const float* c     = (const float*)d_in[2];
    const float* u     = (const float*)d_in[3];
    const float* W     = (const float*)d_in[4];
    const float* blin  = (const float*)d_in[5];
    const float* gamma = (const float*)d_in[6];
    const float* beta  = (const float*)d_in[7];
    float* outH = (float*)d_out;
    float* outC = (float*)d_out + (size_t)BROWS * HDIM;

    cudaFuncSetAttribute(gemm_mma_kernel,
                         cudaFuncAttributeMaxDynamicSharedMemorySize, GEMM_SMEM);

    prep_kernel<<<4096 + 2048, 256>>>(x, h, W);
    gemm_mma_kernel<<<dim3(NDIM / BN, BROWS / BM), 512, GEMM_SMEM>>>(blin);
    fused_tail_kernel<<<BROWS, 256>>>(c, u, gamma, beta, outH, outC);
}

// round 16
// speedup vs baseline: 1.1428x; 1.0123x over previous
#include <cuda_runtime.h>
#include <cuda_fp16.h>
#include <cstdint>
#include <math.h>

// ============================================================================
// FiLMLSTMCell: B=16384, D_IN=512, H=512
// R13 pipeline; GEMM inner loop now software-pipelines fragments (double-
// buffered LDSM issued one ks ahead) to hide the LDSM->MMA dependency stall
// that capped tensor at 50% (R14 ncu). 8 warps, 64x64 warp tiles (traffic-
// optimal per R15's neutral result on 16 warps).
// ============================================================================
#define BROWS 16384
#define KDIM  1024
#define NDIM  2048
#define HDIM  512

__device__ __half g_Ah [(size_t)BROWS * KDIM];  // 32 MB fp16 cat(x,h)
__device__ __half g_WTh[(size_t)NDIM * KDIM];   //  4 MB fp16 W^T [N,K]
__device__ __half g_Zh [(size_t)BROWS * NDIM];  // 64 MB fp16 z

__device__ __forceinline__ void mma_f16(float* c,
                                        uint32_t a0, uint32_t a1, uint32_t a2, uint32_t a3,
                                        uint32_t b0, uint32_t b1) {
    asm volatile(
        "mma.sync.aligned.m16n8k16.row.col.f32.f16.f16.f32 "
        "{%0,%1,%2,%3}, {%4,%5,%6,%7}, {%8,%9}, {%0,%1,%2,%3};"
        : "+f"(c[0]), "+f"(c[1]), "+f"(c[2]), "+f"(c[3])
        : "r"(a0), "r"(a1), "r"(a2), "r"(a3), "r"(b0), "r"(b1));
}

__device__ __forceinline__ void ldsm_x4(uint32_t& r0, uint32_t& r1,
                                        uint32_t& r2, uint32_t& r3, uint32_t addr) {
    asm volatile("ldmatrix.sync.aligned.m8n8.x4.shared.b16 {%0,%1,%2,%3}, [%4];"
                 : "=r"(r0), "=r"(r1), "=r"(r2), "=r"(r3) : "r"(addr));
}

__device__ __forceinline__ float sigm(float x) {
    float e, r;
    asm("ex2.approx.f32 %0, %1;" : "=f"(e) : "f"(-1.4426950408889634f * x));
    asm("rcp.approx.f32 %0, %1;" : "=f"(r) : "f"(1.0f + e));
    return r;
}
__device__ __forceinline__ float tanh_a(float x) {
    float r;
    asm("tanh.approx.f32 %0, %1;" : "=f"(r) : "f"(x));
    return r;
}

// ============================================================================
// GEMM: CTA 128(M) x 256(N), BKH=128, 256 threads (8 warps, 2Mx4N, 64x64),
// 2-stage cp.async, 8 chunks. Swizzle word (row,kp): row*64+(kp^(4*(row&7))).
// Fragments double-buffered: LDSM for ks+1 issued before MMAs of ks.
// ============================================================================
#define BM 128
#define BN 256
#define BKH 128
#define NCHUNK (KDIM / BKH)       // 8
#define STAGES 2

#define A_WORDS (BM * BKH / 2)                 // 8192 words (32KB)
#define B_WORDS (BN * BKH / 2)                 // 16384 (64KB)
#define B_BASE  (STAGES * A_WORDS)             // 16384
#define BIAS_BASE (B_BASE + STAGES * B_WORDS)  // 49152
#define GEMM_SMEM ((BIAS_BASE + BN) * 4)       // 197632 B

__device__ __forceinline__ void load_chunk(uint32_t aBase, uint32_t bBase,
                                           const __half* __restrict__ Asrc,
                                           const __half* __restrict__ Bsrc,
                                           int tid) {
    #pragma unroll
    for (int rep = 0; rep < 8; rep++) {
        int idx = rep * 256 + tid;
        int row = idx >> 4, q = idx & 15;
        uint32_t off = (uint32_t)(row * 256 + 16 * (q ^ (row & 7)));
        asm volatile("cp.async.cg.shared.global [%0], [%1], 16;"
                     :: "r"(aBase + off), "l"(Asrc + (size_t)row * KDIM + q * 8));
    }
    #pragma unroll
    for (int rep = 0; rep < 16; rep++) {
        int idx = rep * 256 + tid;
        int row = idx >> 4, q = idx & 15;
        uint32_t off = (uint32_t)(row * 256 + 16 * (q ^ (row & 7)));
        asm volatile("cp.async.cg.shared.global [%0], [%1], 16;"
                     :: "r"(bBase + off), "l"(Bsrc + (size_t)row * KDIM + q * 8));
    }
    asm volatile("cp.async.commit_group;" ::: "memory");
}

__global__ void __launch_bounds__(256, 1)
gemm_mma_kernel(const float* __restrict__ bias) {
    extern __shared__ float sm[];
    float* sBias = sm + BIAS_BASE;

    const int tid = threadIdx.x, wid = tid >> 5, lane = tid & 31;
    const int g = lane >> 2, l4 = lane & 3;
    const int m0 = blockIdx.y * BM;
    const int n0 = blockIdx.x * BN;
    const int wm = wid & 1, wn = wid >> 1;

    uint32_t sb;
    asm("{ .reg .u64 t; cvta.to.shared.u64 t, %1; cvt.u32.u64 %0, t; }"
        : "=r"(sb) : "l"(sm));

    for (int i = tid; i < BN; i += 256) sBias[i] = bias[n0 + i];

    const int t8 = lane >> 3, rr = lane & 7;
    const int swz = 4 * rr;
    const int rowA = wm * 64 + (t8 & 1) * 8 + rr;
    const int kselA = (t8 >> 1) * 4;
    const int rowB = wn * 64 + (t8 >> 1) * 8 + rr;
    const int kselB = (t8 & 1) * 4;

    float acc[4][8][4];
    #pragma unroll
    for (int a = 0; a < 4; a++)
        #pragma unroll
        for (int b = 0; b < 8; b++)
            #pragma unroll
            for (int d = 0; d < 4; d++) acc[a][b][d] = 0.0f;

    const __half* Ag = g_Ah  + (size_t)m0 * KDIM;
    const __half* Bg = g_WTh + (size_t)n0 * KDIM;

    // double-buffered fragments
    uint32_t afr[2][4][4];
    uint32_t bfr[2][8][2];

    load_chunk(sb, sb + B_BASE * 4, Ag, Bg, tid);

    for (int kc = 0; kc < NCHUNK; kc++) {
        const int s = kc & 1;
        asm volatile("cp.async.wait_group 0;" ::: "memory");
        __syncthreads();

        if (kc + 1 < NCHUNK) {
            const int sl = (kc + 1) & 1;
            load_chunk(sb + sl * A_WORDS * 4, sb + (B_BASE + sl * B_WORDS) * 4,
                       Ag + (kc + 1) * BKH, Bg + (kc + 1) * BKH, tid);
        }

        const uint32_t aSm = sb + (uint32_t)s * A_WORDS * 4;
        const uint32_t bSm = sb + (uint32_t)(B_BASE + s * B_WORDS) * 4;

        // prefetch ks=0 fragments
        {
            const int kwA = kselA ^ swz;
            const int kwB = kselB ^ swz;
            #pragma unroll
            for (int ms = 0; ms < 4; ms++)
                ldsm_x4(afr[0][ms][0], afr[0][ms][1], afr[0][ms][2], afr[0][ms][3],
                        aSm + 4u * ((rowA + ms * 16) * 64 + kwA));
            #pragma unroll
            for (int ns2 = 0; ns2 < 4; ns2++)
                ldsm_x4(bfr[0][2 * ns2][0], bfr[0][2 * ns2][1],
                        bfr[0][2 * ns2 + 1][0], bfr[0][2 * ns2 + 1][1],
                        bSm + 4u * ((rowB + ns2 * 16) * 64 + kwB));
        }

        #pragma unroll
        for (int ks = 0; ks < 8; ks++) {
            const int cur = ks & 1, nxt = cur ^ 1;
            // issue LDSM for ks+1 BEFORE consuming ks -> latency hidden by MMAs
            if (ks < 7) {
                const int kwA = ((ks + 1) * 8 + kselA) ^ swz;
                const int kwB = ((ks + 1) * 8 + kselB) ^ swz;
                #pragma unroll
                for (int ms = 0; ms < 4; ms++)
                    ldsm_x4(afr[nxt][ms][0], afr[nxt][ms][1],
                            afr[nxt][ms][2], afr[nxt][ms][3],
                            aSm + 4u * ((rowA + ms * 16) * 64 + kwA));
                #pragma unroll
                for (int ns2 = 0; ns2 < 4; ns2++)
                    ldsm_x4(bfr[nxt][2 * ns2][0], bfr[nxt][2 * ns2][1],
                            bfr[nxt][2 * ns2 + 1][0], bfr[nxt][2 * ns2 + 1][1],
                            bSm + 4u * ((rowB + ns2 * 16) * 64 + kwB));
            }
            #pragma unroll
            for (int ms = 0; ms < 4; ms++)
                #pragma unroll
                for (int ns = 0; ns < 8; ns++)
                    mma_f16(acc[ms][ns],
                            afr[cur][ms][0], afr[cur][ms][1],
                            afr[cur][ms][2], afr[cur][ms][3],
                            bfr[cur][ns][0], bfr[cur][ns][1]);
        }
    }

    #pragma unroll
    for (int ms = 0; ms < 4; ms++) {
        const int row = m0 + wm * 64 + ms * 16 + g;
        #pragma unroll
        for (int ns = 0; ns < 8; ns++) {
            const int colL = wn * 64 + ns * 8 + 2 * l4;
            const float b0 = sBias[colL], b1 = sBias[colL + 1];
            __half2 v0 = __floats2half2_rn(acc[ms][ns][0] + b0, acc[ms][ns][1] + b1);
            __half2 v1 = __floats2half2_rn(acc[ms][ns][2] + b0, acc[ms][ns][3] + b1);
            *(__half2*)(g_Zh + (size_t)row       * NDIM + n0 + colL) = v0;
            *(__half2*)(g_Zh + (size_t)(row + 8) * NDIM + n0 + colL) = v1;
        }
    }
}

// ============================================================================
// Prep (merged, R13 verbatim)
// ============================================================================
__global__ void __launch_bounds__(256) prep_kernel(const float* __restrict__ x,
                                                   const float* __restrict__ h,
                                                   const float* __restrict__ W) {
    if (blockIdx.x >= 4096) {
        __shared__ float tile[32][33];
        const int wt = blockIdx.x - 4096;
        const int n0 = (wt & 63) * 32, k0 = (wt >> 6) * 32;
        const int tx = threadIdx.x & 31, ty = threadIdx.x >> 5;
        #pragma unroll
        for (int j = 0; j < 32; j += 8)
            tile[ty + j][tx] = W[(size_t)(k0 + ty + j) * NDIM + n0 + tx];
        __syncthreads();
        #pragma unroll
        for (int j = 0; j < 32; j += 8)
            g_WTh[(size_t)(n0 + ty + j) * KDIM + k0 + tx] =
                __float2half_rn(tile[tx][ty + j]);
        return;
    }
    const int base = (blockIdx.x * 256 + threadIdx.x) * 4;
    #pragma unroll
    for (int it = 0; it < 4; it++) {
        const int i = base + it;
        const int m = i >> 8, t = i & 255;
        float4 v;
        if (t < 128) v = ((const float4*)(x + (size_t)m * 512))[t];
        else         v = ((const float4*)(h + (size_t)m * 512))[t - 128];
        __half2 lo = __floats2half2_rn(v.x, v.y);
        __half2 hi = __floats2half2_rn(v.z, v.w);
        uint2 pk = make_uint2(*(uint32_t*)&lo, *(uint32_t*)&hi);
        ((uint2*)(g_Ah + (size_t)m * KDIM))[t] = pk;
    }
}

// ============================================================================
// Fused tail (R13 verbatim)
// ============================================================================
__global__ void __launch_bounds__(256) fused_tail_kernel(
    const float* __restrict__ c, const float* __restrict__ u,
    const float* __restrict__ gamma, const float* __restrict__ beta,
    float* __restrict__ outH, float* __restrict__ outC) {
    __shared__ float s_z[2048];
    __shared__ float s_sum[8], s_sq[8], s_sum2[8], s_sq2[8];

    const int row = blockIdx.x;
    const int t = threadIdx.x, w = t >> 5, lane = t & 31;

    const uint4* zr = (const uint4*)(g_Zh + (size_t)row * 2048);
    const float4* ua = (const float4*)(u + (size_t)row * 4096);
    const float4* ub = (const float4*)(u + (size_t)row * 4096 + 2048);

    uint4 zp = zr[t];
    float2 zf[4];
    zf[0] = __half22float2(*(__half2*)&zp.x);
    zf[1] = __half22float2(*(__half2*)&zp.y);
    zf[2] = __half22float2(*(__half2*)&zp.z);
    zf[3] = __half22float2(*(__half2*)&zp.w);

    float sum = 0.0f, sq = 0.0f;
    #pragma unroll
    for (int q = 0; q < 4; q++) {
        sum += zf[q].x + zf[q].y;
        sq  += zf[q].x * zf[q].x + zf[q].y * zf[q].y;
    }
    #pragma unroll
    for (int o = 16; o; o >>= 1) {
        sum += __shfl_xor_sync(0xFFFFFFFFu, sum, o);
        sq  += __shfl_xor_sync(0xFFFFFFFFu, sq, o);
    }
    if (lane == 0) { s_sum[w] = sum; s_sq[w] = sq; }
    __syncthreads();
    const int grp = t >> 6;
    const float mean = (s_sum[2 * grp] + s_sum[2 * grp + 1]) * (1.0f / 512.0f);
    const float var  = (s_sq[2 * grp] + s_sq[2 * grp + 1]) * (1.0f / 512.0f) - mean * mean;
    const float inv  = rsqrtf(var + 1e-5f);

    float4 a0 = ua[2 * t], a1 = ua[2 * t + 1];
    float4 b0 = ub[2 * t], b1 = ub[2 * t + 1];
    float4 o0, o1;
    o0.x = (zf[0].x - mean) * inv * (1.0f + a0.x) + b0.x;
    o0.y = (zf[0].y - mean) * inv * (1.0f + a0.y) + b0.y;
    o0.z = (zf[1].x - mean) * inv * (1.0f + a0.z) + b0.z;
    o0.w = (zf[1].y - mean) * inv * (1.0f + a0.w) + b0.w;
    o1.x = (zf[2].x - mean) * inv * (1.0f + a1.x) + b1.x;
    o1.y = (zf[2].y - mean) * inv * (1.0f + a1.y) + b1.y;
    o1.z = (zf[3].x - mean) * inv * (1.0f + a1.z) + b1.z;
    o1.w = (zf[3].y - mean) * inv * (1.0f + a1.w) + b1.w;
    ((float4*)s_z)[2 * t] = o0;
    ((float4*)s_z)[2 * t + 1] = o1;
    __syncthreads();

    const int j = 2 * t;
    float2 iz = *(const float2*)&s_z[j];
    float2 fz = *(const float2*)&s_z[512 + j];
    float2 gz = *(const float2*)&s_z[1536 + j];
    float2 cv = *(const float2*)(c + (size_t)row * 512 + j);
    float cn0 = sigm(fz.x) * cv.x + sigm(iz.x) * tanh_a(gz.x);
    float cn1 = sigm(fz.y) * cv.y + sigm(iz.y) * tanh_a(gz.y);
    *(float2*)(outC + (size_t)row * 512 + j) = make_float2(cn0, cn1);

    float sum2 = cn0 + cn1, sq2 = cn0 * cn0 + cn1 * cn1;
    #pragma unroll
    for (int o = 16; o; o >>= 1) {
        sum2 += __shfl_xor_sync(0xFFFFFFFFu, sum2, o);
        sq2  += __shfl_xor_sync(0xFFFFFFFFu, sq2, o);
    }
    if (lane == 0) { s_sum2[w] = sum2; s_sq2[w] = sq2; }
    __syncthreads();

    float ts = 0.0f, tq = 0.0f;
    #pragma unroll
    for (int k = 0; k < 8; k++) { ts += s_sum2[k]; tq += s_sq2[k]; }
    const float m2 = ts * (1.0f / 512.0f);
    const float v2 = tq * (1.0f / 512.0f) - m2 * m2;
    const float inv2 = rsqrtf(v2 + 1e-5f);
    float2 gm = *(const float2*)(gamma + j);
    float2 bt = *(const float2*)(beta + j);
    float cnn0 = (cn0 - m2) * inv2 * gm.x + bt.x;
    float cnn1 = (cn1 - m2) * inv2 * gm.y + bt.y;
    float2 oz = *(const float2*)&s_z[1024 + j];
    float h0 = sigm(oz.x) * tanh_a(cnn0);
    float h1 = sigm(oz.y) * tanh_a(cnn1);
    *(float2*)(outH + (size_t)row * 512 + j) = make_float2(h0, h1);
}

// ============================================================================
// kernel_launch
// ============================================================================
extern "C" void kernel_launch(void* const* d_in, const int* in_sizes, int n_in,
                              void* d_out, int out_size) {
    const float* x     = (const float*)d_in[0];
    const float* h     = (const float*)d_in[1];
    const float* c     = (const float*)d_in[2];
    const float* u     = (const float*)d_in[3];
    const float* W     = (const float*)d_in[4];
    const float* blin  = (const float*)d_in[5];
    const float* gamma = (const float*)d_in[6];
    const float* beta  = (const float*)d_in[7];
    float* outH = (float*)d_out;
    float* outC = (float*)d_out + (size_t)BROWS * HDIM;

    cudaFuncSetAttribute(gemm_mma_kernel,
                         cudaFuncAttributeMaxDynamicSharedMemorySize, GEMM_SMEM);

    prep_kernel<<<4096 + 2048, 256>>>(x, h, W);
    gemm_mma_kernel<<<dim3(NDIM / BN, BROWS / BM), 256, GEMM_SMEM>>>(blin);
    fused_tail_kernel<<<BROWS, 256>>>(c, u, gamma, beta, outH, outC);
}

// round 17
// speedup vs baseline: 1.1534x; 1.0093x over previous
#include <cuda_runtime.h>
#include <cuda_fp16.h>
#include <cstdint>
#include <math.h>

// ============================================================================
// FiLMLSTMCell: B=16384, D_IN=512, H=512
// R13 pipeline at the HMMA issue-rate floor (rt~12cyc/SMSP -> GEMM ~174us).
// This round fixes the edges: coalesced GEMM z-stores via smem repack, and a
// deeper-MLP prep with 16B stores.
// ============================================================================
#define BROWS 16384
#define KDIM  1024
#define NDIM  2048
#define HDIM  512

__device__ __half g_Ah [(size_t)BROWS * KDIM];  // 32 MB fp16 cat(x,h)
__device__ __half g_WTh[(size_t)NDIM * KDIM];   //  4 MB fp16 W^T [N,K]
__device__ __half g_Zh [(size_t)BROWS * NDIM];  // 64 MB fp16 z

__device__ __forceinline__ void mma_f16(float* c,
                                        uint32_t a0, uint32_t a1, uint32_t a2, uint32_t a3,
                                        uint32_t b0, uint32_t b1) {
    asm volatile(
        "mma.sync.aligned.m16n8k16.row.col.f32.f16.f16.f32 "
        "{%0,%1,%2,%3}, {%4,%5,%6,%7}, {%8,%9}, {%0,%1,%2,%3};"
        : "+f"(c[0]), "+f"(c[1]), "+f"(c[2]), "+f"(c[3])
        : "r"(a0), "r"(a1), "r"(a2), "r"(a3), "r"(b0), "r"(b1));
}

__device__ __forceinline__ void ldsm_x4(uint32_t& r0, uint32_t& r1,
                                        uint32_t& r2, uint32_t& r3, uint32_t addr) {
    asm volatile("ldmatrix.sync.aligned.m8n8.x4.shared.b16 {%0,%1,%2,%3}, [%4];"
                 : "=r"(r0), "=r"(r1), "=r"(r2), "=r"(r3) : "r"(addr));
}

__device__ __forceinline__ float sigm(float x) {
    float e, r;
    asm("ex2.approx.f32 %0, %1;" : "=f"(e) : "f"(-1.4426950408889634f * x));
    asm("rcp.approx.f32 %0, %1;" : "=f"(r) : "f"(1.0f + e));
    return r;
}
__device__ __forceinline__ float tanh_a(float x) {
    float r;
    asm("tanh.approx.f32 %0, %1;" : "=f"(r) : "f"(x));
    return r;
}

// ============================================================================
// GEMM: CTA 128(M) x 256(N), BKH=128, 256 threads (8 warps, 2Mx4N, 64x64),
// 2-stage cp.async, 8 chunks. Swizzle word (row,kp): row*64+(kp^(4*(row&7))).
// Epilogue: acc -> smem image (264-half stride, conflict-free) -> uint4 STG.
// ============================================================================
#define BM 128
#define BN 256
#define BKH 128
#define NCHUNK (KDIM / BKH)       // 8
#define STAGES 2

#define A_WORDS (BM * BKH / 2)                 // 8192 words (32KB)
#define B_WORDS (BN * BKH / 2)                 // 16384 (64KB)
#define B_BASE  (STAGES * A_WORDS)             // 16384
#define BIAS_BASE (B_BASE + STAGES * B_WORDS)  // 49152
#define GEMM_SMEM ((BIAS_BASE + BN) * 4)       // 197632 B
#define IMG_STRIDE 264                          // halves per image row

__device__ __forceinline__ void load_chunk(uint32_t aBase, uint32_t bBase,
                                           const __half* __restrict__ Asrc,
                                           const __half* __restrict__ Bsrc,
                                           int tid) {
    #pragma unroll
    for (int rep = 0; rep < 8; rep++) {
        int idx = rep * 256 + tid;
        int row = idx >> 4, q = idx & 15;
        uint32_t off = (uint32_t)(row * 256 + 16 * (q ^ (row & 7)));
        asm volatile("cp.async.cg.shared.global [%0], [%1], 16;"
                     :: "r"(aBase + off), "l"(Asrc + (size_t)row * KDIM + q * 8));
    }
    #pragma unroll
    for (int rep = 0; rep < 16; rep++) {
        int idx = rep * 256 + tid;
        int row = idx >> 4, q = idx & 15;
        uint32_t off = (uint32_t)(row * 256 + 16 * (q ^ (row & 7)));
        asm volatile("cp.async.cg.shared.global [%0], [%1], 16;"
                     :: "r"(bBase + off), "l"(Bsrc + (size_t)row * KDIM + q * 8));
    }
    asm volatile("cp.async.commit_group;" ::: "memory");
}

__global__ void __launch_bounds__(256, 1)
gemm_mma_kernel(const float* __restrict__ bias) {
    extern __shared__ float sm[];
    float* sBias = sm + BIAS_BASE;

    const int tid = threadIdx.x, wid = tid >> 5, lane = tid & 31;
    const int g = lane >> 2, l4 = lane & 3;
    const int m0 = blockIdx.y * BM;
    const int n0 = blockIdx.x * BN;
    const int wm = wid & 1, wn = wid >> 1;

    uint32_t sb;
    asm("{ .reg .u64 t; cvta.to.shared.u64 t, %1; cvt.u32.u64 %0, t; }"
        : "=r"(sb) : "l"(sm));

    for (int i = tid; i < BN; i += 256) sBias[i] = bias[n0 + i];

    const int t8 = lane >> 3, rr = lane & 7;
    const int swz = 4 * rr;
    const int rowA = wm * 64 + (t8 & 1) * 8 + rr;
    const int kselA = (t8 >> 1) * 4;
    const int rowB = wn * 64 + (t8 >> 1) * 8 + rr;
    const int kselB = (t8 & 1) * 4;

    float acc[4][8][4];
    #pragma unroll
    for (int a = 0; a < 4; a++)
        #pragma unroll
        for (int b = 0; b < 8; b++)
            #pragma unroll
            for (int d = 0; d < 4; d++) acc[a][b][d] = 0.0f;

    const __half* Ag = g_Ah  + (size_t)m0 * KDIM;
    const __half* Bg = g_WTh + (size_t)n0 * KDIM;

    load_chunk(sb, sb + B_BASE * 4, Ag, Bg, tid);

    for (int kc = 0; kc < NCHUNK; kc++) {
        const int s = kc & 1;
        asm volatile("cp.async.wait_group 0;" ::: "memory");
        __syncthreads();

        if (kc + 1 < NCHUNK) {
            const int sl = (kc + 1) & 1;
            load_chunk(sb + sl * A_WORDS * 4, sb + (B_BASE + sl * B_WORDS) * 4,
                       Ag + (kc + 1) * BKH, Bg + (kc + 1) * BKH, tid);
        }

        const uint32_t aSm = sb + (uint32_t)s * A_WORDS * 4;
        const uint32_t bSm = sb + (uint32_t)(B_BASE + s * B_WORDS) * 4;

        #pragma unroll
        for (int ks = 0; ks < 8; ks++) {
            const int kwA = (ks * 8 + kselA) ^ swz;
            const int kwB = (ks * 8 + kselB) ^ swz;
            uint32_t afr[4][4];
            #pragma unroll
            for (int ms = 0; ms < 4; ms++)
                ldsm_x4(afr[ms][0], afr[ms][1], afr[ms][2], afr[ms][3],
                        aSm + 4u * ((rowA + ms * 16) * 64 + kwA));
            uint32_t bfr[8][2];
            #pragma unroll
            for (int ns2 = 0; ns2 < 4; ns2++)
                ldsm_x4(bfr[2 * ns2][0], bfr[2 * ns2][1],
                        bfr[2 * ns2 + 1][0], bfr[2 * ns2 + 1][1],
                        bSm + 4u * ((rowB + ns2 * 16) * 64 + kwB));
            #pragma unroll
            for (int ms = 0; ms < 4; ms++)
                #pragma unroll
                for (int ns = 0; ns < 8; ns++)
                    mma_f16(acc[ms][ns], afr[ms][0], afr[ms][1], afr[ms][2], afr[ms][3],
                            bfr[ns][0], bfr[ns][1]);
        }
    }

    // ---- Epilogue: repack through smem, then fully-coalesced uint4 stores
    __syncthreads();                      // all LDSM reads of stages done
    __half* simg = (__half*)sm;           // 128 x IMG_STRIDE fp16 image (~66KB)
    #pragma unroll
    for (int ms = 0; ms < 4; ms++) {
        const int rl = wm * 64 + ms * 16 + g;
        #pragma unroll
        for (int ns = 0; ns < 8; ns++) {
            const int colL = wn * 64 + ns * 8 + 2 * l4;
            const float b0 = sBias[colL], b1 = sBias[colL + 1];
            __half2 v0 = __floats2half2_rn(acc[ms][ns][0] + b0, acc[ms][ns][1] + b1);
            __half2 v1 = __floats2half2_rn(acc[ms][ns][2] + b0, acc[ms][ns][3] + b1);
            *(__half2*)&simg[rl * IMG_STRIDE + colL] = v0;
            *(__half2*)&simg[(rl + 8) * IMG_STRIDE + colL] = v1;
        }
    }
    __syncthreads();
    // 128 rows x 32 uint4 (512B/row), 16 iterations of 256 threads
    #pragma unroll
    for (int it = 0; it < 16; it++) {
        const int i = it * 256 + tid;
        const int row = i >> 5, q = i & 31;
        uint4 v = ((const uint4*)simg)[row * (IMG_STRIDE / 8) + q];
        ((uint4*)(g_Zh + (size_t)(m0 + row) * NDIM + n0))[q] = v;
    }
}

// ============================================================================
// Prep (merged, one launch): blocks <2048 convert cat(x,h)->fp16 (8 float4
// loads -> 4 uint4 stores per thread); blocks >=2048 transpose+convert W.
// ============================================================================
__global__ void __launch_bounds__(256) prep_kernel(const float* __restrict__ x,
                                                   const float* __restrict__ h,
                                                   const float* __restrict__ W) {
    if (blockIdx.x >= 2048) {
        __shared__ float tile[32][33];
        const int wt = blockIdx.x - 2048;          // 0..2047
        const int n0 = (wt & 63) * 32, k0 = (wt >> 6) * 32;
        const int tx = threadIdx.x & 31, ty = threadIdx.x >> 5;  // (32,8)
        #pragma unroll
        for (int j = 0; j < 32; j += 8)
            tile[ty + j][tx] = W[(size_t)(k0 + ty + j) * NDIM + n0 + tx];
        __syncthreads();
        #pragma unroll
        for (int j = 0; j < 32; j += 8)
            g_WTh[(size_t)(n0 + ty + j) * KDIM + k0 + tx] =
                __float2half_rn(tile[tx][ty + j]);
        return;
    }
    // A part: float4-task base; 8 consecutive tasks per thread (one row part)
    const int base = (blockIdx.x * 256 + threadIdx.x) * 8;
    const int m = base >> 8;          // row
    const int p = base & 255;         // float4 position in cat-row
    const float4* src = (p < 128)
        ? ((const float4*)(x + (size_t)m * 512) + p)
        : ((const float4*)(h + (size_t)m * 512) + (p - 128));
    uint4* dst = (uint4*)(g_Ah + (size_t)m * KDIM) + (p >> 1);
    #pragma unroll
    for (int j = 0; j < 4; j++) {
        float4 v0 = src[2 * j], v1 = src[2 * j + 1];
        __half2 ha = __floats2half2_rn(v0.x, v0.y);
        __half2 hb = __floats2half2_rn(v0.z, v0.w);
        __half2 hc = __floats2half2_rn(v1.x, v1.y);
        __half2 hd = __floats2half2_rn(v1.z, v1.w);
        dst[j] = make_uint4(*(uint32_t*)&ha, *(uint32_t*)&hb,
                            *(uint32_t*)&hc, *(uint32_t*)&hd);
    }
}

// ============================================================================
// Fused tail (R13 verbatim): GN4+FiLM+gates+c_new+GN1+h_new, 1 CTA / row
// ============================================================================
__global__ void __launch_bounds__(256) fused_tail_kernel(
    const float* __restrict__ c, const float* __restrict__ u,
    const float* __restrict__ gamma, const float* __restrict__ beta,
    float* __restrict__ outH, float* __restrict__ outC) {
    __shared__ float s_z[2048];
    __shared__ float s_sum[8], s_sq[8], s_sum2[8], s_sq2[8];

    const int row = blockIdx.x;
    const int t = threadIdx.x, w = t >> 5, lane = t & 31;

    const uint4* zr = (const uint4*)(g_Zh + (size_t)row * 2048);
    const float4* ua = (const float4*)(u + (size_t)row * 4096);
    const float4* ub = (const float4*)(u + (size_t)row * 4096 + 2048);

    uint4 zp = zr[t];
    float2 zf[4];
    zf[0] = __half22float2(*(__half2*)&zp.x);
    zf[1] = __half22float2(*(__half2*)&zp.y);
    zf[2] = __half22float2(*(__half2*)&zp.z);
    zf[3] = __half22float2(*(__half2*)&zp.w);

    float sum = 0.0f, sq = 0.0f;
    #pragma unroll
    for (int q = 0; q < 4; q++) {
        sum += zf[q].x + zf[q].y;
        sq  += zf[q].x * zf[q].x + zf[q].y * zf[q].y;
    }
    #pragma unroll
    for (int o = 16; o; o >>= 1) {
        sum += __shfl_xor_sync(0xFFFFFFFFu, sum, o);
        sq  += __shfl_xor_sync(0xFFFFFFFFu, sq, o);
    }
    if (lane == 0) { s_sum[w] = sum; s_sq[w] = sq; }
    __syncthreads();
    const int grp = t >> 6;
    const float mean = (s_sum[2 * grp] + s_sum[2 * grp + 1]) * (1.0f / 512.0f);
    const float var  = (s_sq[2 * grp] + s_sq[2 * grp + 1]) * (1.0f / 512.0f) - mean * mean;
    const float inv  = rsqrtf(var + 1e-5f);

    float4 a0 = ua[2 * t], a1 = ua[2 * t + 1];
    float4 b0 = ub[2 * t], b1 = ub[2 * t + 1];
    float4 o0, o1;
    o0.x = (zf[0].x - mean) * inv * (1.0f + a0.x) + b0.x;
    o0.y = (zf[0].y - mean) * inv * (1.0f + a0.y) + b0.y;
    o0.z = (zf[1].x - mean) * inv * (1.0f + a0.z) + b0.z;
    o0.w = (zf[1].y - mean) * inv * (1.0f + a0.w) + b0.w;
    o1.x = (zf[2].x - mean) * inv * (1.0f + a1.x) + b1.x;
    o1.y = (zf[2].y - mean) * inv * (1.0f + a1.y) + b1.y;
    o1.z = (zf[3].x - mean) * inv * (1.0f + a1.z) + b1.z;
    o1.w = (zf[3].y - mean) * inv * (1.0f + a1.w) + b1.w;
    ((float4*)s_z)[2 * t] = o0;
    ((float4*)s_z)[2 * t + 1] = o1;
    __syncthreads();

    const int j = 2 * t;
    float2 iz = *(const float2*)&s_z[j];
    float2 fz = *(const float2*)&s_z[512 + j];
    float2 gz = *(const float2*)&s_z[1536 + j];
    float2 cv = *(const float2*)(c + (size_t)row * 512 + j);
    float cn0 = sigm(fz.x) * cv.x + sigm(iz.x) * tanh_a(gz.x);
    float cn1 = sigm(fz.y) * cv.y + sigm(iz.y) * tanh_a(gz.y);
    *(float2*)(outC + (size_t)row * 512 + j) = make_float2(cn0, cn1);

    float sum2 = cn0 + cn1, sq2 = cn0 * cn0 + cn1 * cn1;
    #pragma unroll
    for (int o = 16; o; o >>= 1) {
        sum2 += __shfl_xor_sync(0xFFFFFFFFu, sum2, o);
        sq2  += __shfl_xor_sync(0xFFFFFFFFu, sq2, o);
    }
    if (lane == 0) { s_sum2[w] = sum2; s_sq2[w] = sq2; }
    __syncthreads();

    float ts = 0.0f, tq = 0.0f;
    #pragma unroll
    for (int k = 0; k < 8; k++) { ts += s_sum2[k]; tq += s_sq2[k]; }
    const float m2 = ts * (1.0f / 512.0f);
    const float v2 = tq * (1.0f / 512.0f) - m2 * m2;
    const float inv2 = rsqrtf(v2 + 1e-5f);
    float2 gm = *(const float2*)(gamma + j);
    float2 bt = *(const float2*)(beta + j);
    float cnn0 = (cn0 - m2) * inv2 * gm.x + bt.x;
    float cnn1 = (cn1 - m2) * inv2 * gm.y + bt.y;
    float2 oz = *(const float2*)&s_z[1024 + j];
    float h0 = sigm(oz.x) * tanh_a(cnn0);
    float h1 = sigm(oz.y) * tanh_a(cnn1);
    *(float2*)(outH + (size_t)row * 512 + j) = make_float2(h0, h1);
}

// ============================================================================
// kernel_launch
// ============================================================================
extern "C" void kernel_launch(void* const* d_in, const int* in_sizes, int n_in,
                              void* d_out, int out_size) {
    const float* x     = (const float*)d_in[0];
    const float* h     = (const float*)d_in[1];
    const float* c     = (const float*)d_in[2];
    const float* u     = (const float*)d_in[3];
    const float* W     = (const float*)d_in[4];
    const float* blin  = (const float*)d_in[5];
    const float* gamma = (const float*)d_in[6];
    const float* beta  = (const float*)d_in[7];
    float* outH = (float*)d_out;
    float* outC = (float*)d_out + (size_t)BROWS * HDIM;

    cudaFuncSetAttribute(gemm_mma_kernel,
                         cudaFuncAttributeMaxDynamicSharedMemorySize, GEMM_SMEM);

    prep_kernel<<<2048 + 2048, 256>>>(x, h, W);
    gemm_mma_kernel<<<dim3(NDIM / BN, BROWS / BM), 256, GEMM_SMEM>>>(blin);
    fused_tail_kernel<<<BROWS, 256>>>(c, u, gamma, beta, outH, outC);
}